// round 16
// baseline (speedup 1.0000x reference)
#include <cuda_runtime.h>
#include <cuda_bf16.h>

#define BB 16384
#define SS 4
#define LL 16
#define DD 256
#define BOS_ID 98
#define OUTROWS (BB * 5)         // 81920
#define ROWB 1024                // bytes per output row

typedef unsigned long long u64;

struct V8 { u64 x, y, z, w; };   // 8 floats = 32 bytes

__device__ __forceinline__ V8 ldg256(const void* p) {
    V8 v;
    asm volatile("ld.global.nc.v4.b64 {%0,%1,%2,%3}, [%4];"
                 : "=l"(v.x), "=l"(v.y), "=l"(v.z), "=l"(v.w) : "l"(p));
    return v;
}
// Streaming 256-bit store: one warp-wide instruction covers a full 1KB row.
__device__ __forceinline__ void stg256cs(void* p, V8 v) {
    asm volatile("st.global.cs.v4.b64 [%0], {%1,%2,%3,%4};"
                 :: "l"(p), "l"(v.x), "l"(v.y), "l"(v.z), "l"(v.w) : "memory");
}
__device__ __forceinline__ void add2(u64& a, u64 e) {
    asm("add.rn.f32x2 %0, %0, %1;" : "+l"(a) : "l"(e));
}
__device__ __forceinline__ void fma2(u64& a, u64 m, u64 e) {
    asm("fma.rn.f32x2 %0, %1, %2, %0;" : "+l"(a) : "l"(m), "l"(e));
}
__device__ __forceinline__ u64 dup2(float m) {
    u64 r; asm("mov.b64 %0, {%1, %1};" : "=l"(r) : "f"(m)); return r;
}
__device__ __forceinline__ void mul2(u64& a, u64 m) {
    asm("mul.rn.f32x2 %0, %0, %1;" : "+l"(a) : "l"(m));
}

// One warp per output row of (B, 5, 256). Lane owns bytes [lane*32, lane*32+32).
__global__ void __launch_bounds__(128) actions_emb_kernel(
    const int*  __restrict__ char_ids,     // (B, S, L)
    const int*  __restrict__ char_len,     // (B, S)
    const int*  __restrict__ action_ids,   // (B, S)
    const int*  __restrict__ slot_type,    // (B, S)
    const char* __restrict__ char_table,   // (N_CHAR, 256) fp32 rows = 1KB each
    const char* __restrict__ action_table, // (N_ACT, 256)
    char*       __restrict__ out)          // (B, 5, 256)
{
    const int gtid = blockIdx.x * blockDim.x + threadIdx.x;
    const int row  = gtid >> 5;
    const int lane = gtid & 31;
    if (row >= OUTROWS) return;

    const int s = row % 5;
    const int b = row / 5;
    const int off = lane * 32;              // this lane's byte slice of the row

    V8 r;

    if (s == 0) {
        // BOS: action_table row 98, L1-hot.
        r = ldg256(action_table + BOS_ID * ROWB + off);
    } else {
        const int bs = b * SS + (s - 1);
        // 7 independent control loads -> one DRAM round-trip.
        const int  st  = __ldg(&slot_type[bs]);
        const int  len = __ldg(&char_len[bs]);          // 1..15
        const int  ai  = __ldg(&action_ids[bs]);
        const int4* p  = (const int4*)(char_ids + bs * LL);
        const int4 i0  = __ldg(&p[0]);
        const int4 i1  = __ldg(&p[1]);
        const int4 i2  = __ldg(&p[2]);
        const int4 i3  = __ldg(&p[3]);

        if (st == 0) {
            u64 ax = 0, ay = 0, az = 0, aw = 0;
            // Pair (ia, ib): ia guaranteed valid when base < len; ib masked.
            #define GPAIR(ia, ib, base)                                          \
            if (len > (base)) {                                                  \
                const V8 ea = ldg256(char_table + (ia) * ROWB + off);            \
                const V8 eb = ldg256(char_table + (ib) * ROWB + off);            \
                add2(ax, ea.x); add2(ay, ea.y); add2(az, ea.z); add2(aw, ea.w);  \
                const u64 m = dup2(((base) + 1 < len) ? 1.0f : 0.0f);            \
                fma2(ax, m, eb.x); fma2(ay, m, eb.y);                            \
                fma2(az, m, eb.z); fma2(aw, m, eb.w);                            \
            }
            GPAIR(i0.x, i0.y,  0)
            GPAIR(i0.z, i0.w,  2)
            GPAIR(i1.x, i1.y,  4)
            GPAIR(i1.z, i1.w,  6)
            GPAIR(i2.x, i2.y,  8)
            GPAIR(i2.z, i2.w, 10)
            GPAIR(i3.x, i3.y, 12)
            GPAIR(i3.z, i3.w, 14)
            #undef GPAIR
            const u64 inv = dup2(1.0f / (float)len);
            mul2(ax, inv); mul2(ay, inv); mul2(az, inv); mul2(aw, inv);
            r.x = ax; r.y = ay; r.z = az; r.w = aw;
        } else if (st == 1) {
            r = ldg256(action_table + ai * ROWB + off);
        } else {
            r.x = 0; r.y = 0; r.z = 0; r.w = 0;
        }
    }

    stg256cs(out + (long long)row * ROWB + off, r);
}

extern "C" void kernel_launch(void* const* d_in, const int* in_sizes, int n_in,
                              void* d_out, int out_size)
{
    const int*  char_ids     = (const int*) d_in[0];
    const int*  char_len     = (const int*) d_in[1];
    const int*  action_ids   = (const int*) d_in[2];
    const int*  slot_type    = (const int*) d_in[3];
    const char* char_table   = (const char*)d_in[4];
    const char* action_table = (const char*)d_in[5];
    char*       out          = (char*)      d_out;

    const int threads = 128;                       // 4 warps per block
    const int blocks  = (OUTROWS * 32) / threads;  // 20480
    actions_emb_kernel<<<blocks, threads>>>(char_ids, char_len, action_ids,
                                            slot_type, char_table, action_table, out);
}